// round 8
// baseline (speedup 1.0000x reference)
#include <cuda_runtime.h>
#include <cuda_fp16.h>
#include <mma.h>
#include <cstdint>

using namespace nvcuda;

#define TOK 16384
#define HDIM 1024
#define IDIM 3584
#define NEXP 8
#define MAXROWS 33792
#define MAXMT 264
#define WELEM 29360128LL

static __device__ __half g_x16[(size_t)TOK * HDIM];
static __device__ __half g_hid[(size_t)MAXROWS * IDIM];
static __device__ __half g_y [(size_t)MAXROWS * HDIM];
static __device__ int   g_sel[TOK * 2];
static __device__ float g_wgt[TOK * 2];
static __device__ int   g_rowof[TOK * 2];
static __device__ int   g_rowtok[MAXROWS];
static __device__ int   g_cnt[NEXP], g_cur[NEXP], g_base[NEXP], g_mtp[NEXP + 1];
static __device__ float g_stat[3];
static __device__ int   g_slotw1, g_slotw2, g_slotw3;

__device__ __forceinline__ float silu_f(float x) { return x / (1.f + __expf(-x)); }

__global__ void sentinel_kernel(float* __restrict__ out) {
    size_t i = ((size_t)blockIdx.x * 256 + threadIdx.x) * 4;
    float4 v = make_float4(100.f, 100.f, 100.f, 100.f);
    *(float4*)(out + i) = v;
}
__global__ void init_kernel() {
    int i = threadIdx.x;
    if (i < NEXP) { g_cnt[i] = 0; g_cur[i] = 0; }
    if (i < 3) g_stat[i] = 0.f;
}
__global__ void fill_rowtok_kernel() {
    int i = blockIdx.x * 256 + threadIdx.x;
    if (i < MAXROWS) g_rowtok[i] = 0;
}
// mean-|.| sample of each weight candidate; w2 (scaled 1/sqrt(I)) has the smallest
__global__ void stat_kernel(const float* t0, const float* t1, const float* t2) {
    const float* p = blockIdx.x == 0 ? t0 : (blockIdx.x == 1 ? t1 : t2);
    if (!p) return;
    float s = 0.f;
    for (int i = threadIdx.x; i < 65536; i += 256) s += fabsf(p[(size_t)i * 448]);
    for (int o = 16; o; o >>= 1) s += __shfl_xor_sync(0xFFFFFFFFu, s, o);
    __shared__ float ws[8];
    if ((threadIdx.x & 31) == 0) ws[threadIdx.x >> 5] = s;
    __syncthreads();
    if (threadIdx.x == 0) {
        float t = 0.f;
        for (int w = 0; w < 8; w++) t += ws[w];
        g_stat[blockIdx.x] = t;
    }
}
__global__ void pick_kernel() {
    if (threadIdx.x == 0) {
        float a = g_stat[0], b = g_stat[1], c = g_stat[2];
        int w2 = (a <= b && a <= c) ? 0 : ((b <= c) ? 1 : 2);
        int f = -1, s = -1;
        for (int i = 0; i < 3; i++) if (i != w2) { if (f < 0) f = i; else s = i; }
        g_slotw2 = w2; g_slotw1 = f; g_slotw3 = s;
    }
}
__global__ void cvtx_kernel(const float* __restrict__ x) {
    if (!x) return;
    size_t i = ((size_t)blockIdx.x * 256 + threadIdx.x) * 4;
    float4 v = *(const float4*)(x + i);
    *reinterpret_cast<__half2*>(g_x16 + i)     = __floats2half2_rn(v.x, v.y);
    *reinterpret_cast<__half2*>(g_x16 + i + 2) = __floats2half2_rn(v.z, v.w);
}
__global__ void router_kernel(const float* __restrict__ x, const float* __restrict__ gw) {
    if (!x || !gw) return;
    __shared__ float gsm[NEXP * HDIM];
    int tid = threadIdx.x;
    for (int i = tid; i < NEXP * HDIM; i += 256) gsm[i] = gw[i];
    __syncthreads();
    int t = blockIdx.x * 8 + (tid >> 5), lane = tid & 31;
    const float* xr = x + (size_t)t * HDIM;
    float acc[NEXP];
#pragma unroll
    for (int e = 0; e < NEXP; e++) acc[e] = 0.f;
    for (int h = lane; h < HDIM; h += 32) {
        float xv = xr[h];
#pragma unroll
        for (int e = 0; e < NEXP; e++) acc[e] += xv * gsm[e * HDIM + h];
    }
#pragma unroll
    for (int e = 0; e < NEXP; e++)
        for (int o = 16; o; o >>= 1) acc[e] += __shfl_xor_sync(0xFFFFFFFFu, acc[e], o);
    if (lane == 0) {
        float m = acc[0];
#pragma unroll
        for (int e = 1; e < NEXP; e++) m = fmaxf(m, acc[e]);
        float p[NEXP];
#pragma unroll
        for (int e = 0; e < NEXP; e++) p[e] = __expf(acc[e] - m);
        int i0 = 0;
#pragma unroll
        for (int e = 1; e < NEXP; e++) if (p[e] > p[i0]) i0 = e;
        int i1 = (i0 == 0) ? 1 : 0;
#pragma unroll
        for (int e = 0; e < NEXP; e++) if (e != i0 && e != i1 && p[e] > p[i1]) i1 = e;
        float inv = 1.f / (p[i0] + p[i1]);
        g_sel[2 * t] = i0; g_sel[2 * t + 1] = i1;
        g_wgt[2 * t] = p[i0] * inv; g_wgt[2 * t + 1] = p[i1] * inv;
        atomicAdd(&g_cnt[i0], 1); atomicAdd(&g_cnt[i1], 1);
    }
}
__global__ void scan_kernel() {
    if (threadIdx.x == 0) {
        int tot = 0, mt = 0;
        g_mtp[0] = 0;
        for (int e = 0; e < NEXP; e++) {
            g_base[e] = tot;
            int pc = (g_cnt[e] + 127) & ~127;
            tot += pc; mt += pc >> 7;
            g_mtp[e + 1] = mt;
        }
    }
}
__global__ void scatter_kernel() {
    int p = blockIdx.x * 256 + threadIdx.x;
    if (p >= TOK * 2) return;
    int e = g_sel[p];
    int r = g_base[e] + atomicAdd(&g_cur[e], 1);
    g_rowtok[r] = p >> 1;
    g_rowof[p] = r;
}
__global__ void combine_kernel(float* __restrict__ out) {
    int idx = blockIdx.x * 256 + threadIdx.x;
    int t = idx >> 7, seg = idx & 127;
    int r0 = g_rowof[2 * t], r1 = g_rowof[2 * t + 1];
    float w0 = g_wgt[2 * t], w1 = g_wgt[2 * t + 1];
    const __half2* y0 = (const __half2*)(g_y + ((size_t)r0 << 10) + seg * 8);
    const __half2* y1 = (const __half2*)(g_y + ((size_t)r1 << 10) + seg * 8);
    float* dst = out + ((size_t)t << 10) + seg * 8;
#pragma unroll
    for (int j = 0; j < 4; j++) {
        float2 a = __half22float2(y0[j]);
        float2 b = __half22float2(y1[j]);
        dst[2 * j]     = w0 * a.x + w1 * b.x;
        dst[2 * j + 1] = w0 * a.y + w1 * b.y;
    }
}

// WMMA grouped GEMM. CTA 128(M)x64(N), BK=32; weights read fp32 + converted in-register.
// Layouts are natural [E][K][N]: w1/w3 = [E][H][I], w2 = [E][I][H]. No transposes.
// grid: x = m-tile (B-tile reuse across same-n waves), y = n-tile.
template <int FUSED>
__global__ void __launch_bounds__(256) wmma_gemm_kernel(const float* t0, const float* t1, const float* t2) {
    __shared__ __align__(16) __half sA[128 * 40];
    __shared__ __align__(16) __half sB1[32 * 72];
    __shared__ __align__(16) __half sB3[FUSED ? 32 * 72 : 8];
    __shared__ __align__(16) float estage[8][2][256];

    const int tid = threadIdx.x, wid = tid >> 5, lane = tid & 31;
    const int gm = blockIdx.x;
    if (gm >= g_mtp[NEXP]) return;
    int e = 0;
    while (e < NEXP - 1 && gm >= g_mtp[e + 1]) e++;
    const int row0 = g_base[e] + (gm - g_mtp[e]) * 128;
    const int n0 = blockIdx.y * 64;
    const int KD = FUSED ? HDIM : IDIM;
    const int ND = FUSED ? IDIM : HDIM;

    const float* wsel0 = t0; const float* wsel1 = t1; const float* wsel2 = t2;
    const int s1 = FUSED ? g_slotw1 : g_slotw2;
    const float* B1f = s1 == 0 ? wsel0 : (s1 == 1 ? wsel1 : wsel2);
    const float* B3f = nullptr;
    if (FUSED) {
        const int s3 = g_slotw3;
        B3f = s3 == 0 ? wsel0 : (s3 == 1 ? wsel1 : wsel2);
    }
    if (!B1f || (FUSED && !B3f)) return;
    const float* B1base = B1f + (size_t)e * HDIM * IDIM + n0;
    const float* B3base = FUSED ? B3f + (size_t)e * HDIM * IDIM + n0 : nullptr;

    const int arow = tid >> 1, acol = (tid & 1) * 16;
    const __half* aRow = FUSED ? g_x16 + (size_t)g_rowtok[row0 + arow] * HDIM
                               : g_hid + (size_t)(row0 + arow) * IDIM;
    const int bk = tid >> 3, bn = (tid & 7) * 8;

    const int wm = wid & 3, wn = wid >> 2;
    wmma::fragment<wmma::accumulator, 16, 16, 16, float> c1[2][2], c3[FUSED ? 2 : 1][FUSED ? 2 : 1];
#pragma unroll
    for (int mi = 0; mi < 2; mi++)
#pragma unroll
        for (int ni = 0; ni < 2; ni++) {
            wmma::fill_fragment(c1[mi][ni], 0.f);
            if (FUSED) wmma::fill_fragment(c3[mi][ni], 0.f);
        }

    for (int k0 = 0; k0 < KD; k0 += 32) {
        __syncthreads();
        {
            const uint4* s = (const uint4*)(aRow + k0 + acol);
            uint4* d = (uint4*)(sA + arow * 40 + acol);
            d[0] = s[0]; d[1] = s[1];
            const float4* s1p = (const float4*)(B1base + (size_t)(k0 + bk) * ND + bn);
            float4 v0 = s1p[0], v1 = s1p[1];
            __half2* d1 = (__half2*)(sB1 + bk * 72 + bn);
            d1[0] = __floats2half2_rn(v0.x, v0.y); d1[1] = __floats2half2_rn(v0.z, v0.w);
            d1[2] = __floats2half2_rn(v1.x, v1.y); d1[3] = __floats2half2_rn(v1.z, v1.w);
            if (FUSED) {
                const float4* s3p = (const float4*)(B3base + (size_t)(k0 + bk) * ND + bn);
                float4 u0 = s3p[0], u1 = s3p[1];
                __half2* d3 = (__half2*)(sB3 + bk * 72 + bn);
                d3[0] = __floats2half2_rn(u0.x, u0.y); d3[1] = __floats2half2_rn(u0.z, u0.w);
                d3[2] = __floats2half2_rn(u1.x, u1.y); d3[3] = __floats2half2_rn(u1.z, u1.w);
            }
        }
        __syncthreads();
#pragma unroll
        for (int ks = 0; ks < 2; ks++) {
            wmma::fragment<wmma::matrix_a, 16, 16, 16, __half, wmma::row_major> af[2];
#pragma unroll
            for (int mi = 0; mi < 2; mi++)
                wmma::load_matrix_sync(af[mi], sA + (wm * 32 + mi * 16) * 40 + ks * 16, 40);
#pragma unroll
            for (int ni = 0; ni < 2; ni++) {
                wmma::fragment<wmma::matrix_b, 16, 16, 16, __half, wmma::row_major> bf;
                wmma::load_matrix_sync(bf, sB1 + ks * 16 * 72 + wn * 32 + ni * 16, 72);
#pragma unroll
                for (int mi = 0; mi < 2; mi++)
                    wmma::mma_sync(c1[mi][ni], af[mi], bf, c1[mi][ni]);
                if (FUSED) {
                    wmma::fragment<wmma::matrix_b, 16, 16, 16, __half, wmma::row_major> bf3;
                    wmma::load_matrix_sync(bf3, sB3 + ks * 16 * 72 + wn * 32 + ni * 16, 72);
#pragma unroll
                    for (int mi = 0; mi < 2; mi++)
                        wmma::mma_sync(c3[mi][ni], af[mi], bf3, c3[mi][ni]);
                }
            }
        }
    }

    __half* ob = FUSED ? g_hid : g_y;
#pragma unroll
    for (int mi = 0; mi < 2; mi++)
#pragma unroll
        for (int ni = 0; ni < 2; ni++) {
            wmma::store_matrix_sync(estage[wid][0], c1[mi][ni], 16, wmma::mem_row_major);
            if (FUSED) wmma::store_matrix_sync(estage[wid][1], c3[mi][ni], 16, wmma::mem_row_major);
            __syncwarp();
            const size_t rbase = (size_t)(row0 + wm * 32 + mi * 16);
            const int cbase = n0 + wn * 32 + ni * 16;
#pragma unroll
            for (int j = 0; j < 8; j++) {
                int idx = lane * 8 + j;
                int rr = idx >> 4, cc = idx & 15;
                float v = estage[wid][0][idx];
                float hv = FUSED ? silu_f(v) * estage[wid][1][idx] : v;
                ob[(rbase + rr) * (size_t)ND + cbase + cc] = __float2half_rn(hv);
            }
            __syncwarp();
        }
}

extern "C" void kernel_launch(void* const* d_in, const int* in_sizes, int n_in,
                              void* d_out, int out_size) {
    // Resolve inputs by size: accept ELEMENT or BYTE counts; fall back to positional dict order.
    const float* x = nullptr; const float* gw = nullptr;
    const float* trio[3] = {nullptr, nullptr, nullptr};
    int ntrio = 0;
    for (int i = 0; i < n_in; i++) {
        long long s = in_sizes[i];
        if (s == 16777216LL || s == 67108864LL) { if (!x) x = (const float*)d_in[i]; }
        else if (s == 8192LL || s == 32768LL) { if (!gw) gw = (const float*)d_in[i]; }
        else if ((s == WELEM || s == WELEM * 4) && ntrio < 3) trio[ntrio++] = (const float*)d_in[i];
    }
    if (!x || !gw || ntrio != 3) {  // positional fallback: setup_inputs dict order
        if (n_in >= 5) {
            x = (const float*)d_in[0]; gw = (const float*)d_in[1];
            trio[0] = (const float*)d_in[2]; trio[1] = (const float*)d_in[3];
            trio[2] = (const float*)d_in[4]; ntrio = 3;
        }
    }
    float* out = (float*)d_out;

    sentinel_kernel<<<TOK * HDIM / 1024, 256>>>(out);
    init_kernel<<<1, 32>>>();
    fill_rowtok_kernel<<<(MAXROWS + 255) / 256, 256>>>();
    stat_kernel<<<3, 256>>>(trio[0], trio[1], trio[2]);
    pick_kernel<<<1, 32>>>();
    cvtx_kernel<<<TOK * HDIM / 1024, 256>>>(x);
    router_kernel<<<TOK / 8, 256>>>(x, gw);
    scan_kernel<<<1, 1>>>();
    scatter_kernel<<<TOK * 2 / 256, 256>>>();
    wmma_gemm_kernel<1><<<dim3(MAXMT, IDIM / 64), 256>>>(trio[0], trio[1], trio[2]);
    wmma_gemm_kernel<0><<<dim3(MAXMT, HDIM / 64), 256>>>(trio[0], trio[1], trio[2]);
    combine_kernel<<<TOK * 128 / 256, 256>>>(out);
}

// round 9
// speedup vs baseline: 1.0778x; 1.0778x over previous
#include <cuda_runtime.h>
#include <cuda_fp16.h>
#include <mma.h>
#include <cstdint>

using namespace nvcuda;

#define TOK 16384
#define HDIM 1024
#define IDIM 3584
#define NEXP 8
#define MAXROWS 33792
#define MAXMT 264
#define WELEM 29360128LL

static __device__ __half g_x16[(size_t)TOK * HDIM];
static __device__ __half g_hid[(size_t)MAXROWS * IDIM];
static __device__ __half g_y [(size_t)MAXROWS * HDIM];
static __device__ int   g_sel[TOK * 2];
static __device__ float g_wgt[TOK * 2];
static __device__ int   g_rowof[TOK * 2];
static __device__ int   g_rowtok[MAXROWS];
static __device__ int   g_cnt[NEXP], g_cur[NEXP], g_base[NEXP], g_mtp[NEXP + 1];
static __device__ float g_stat[3];
static __device__ int   g_slotw1, g_slotw2, g_slotw3;

__device__ __forceinline__ float silu_f(float x) { return x / (1.f + __expf(-x)); }

__global__ void sentinel_kernel(float* __restrict__ out) {
    size_t i = ((size_t)blockIdx.x * 256 + threadIdx.x) * 4;
    *(float4*)(out + i) = make_float4(100.f, 100.f, 100.f, 100.f);
}
__global__ void init_kernel() {
    int i = threadIdx.x;
    if (i < NEXP) { g_cnt[i] = 0; g_cur[i] = 0; }
    if (i < 3) g_stat[i] = 0.f;
}
__global__ void fill_rowtok_kernel() {
    int i = blockIdx.x * 256 + threadIdx.x;
    if (i < MAXROWS) g_rowtok[i] = 0;
}
// mean-|.| sample; w2 (scaled 1/sqrt(I), I=3.5H) has the smallest
__global__ void stat_kernel(const float* t0, const float* t1, const float* t2) {
    const float* p = blockIdx.x == 0 ? t0 : (blockIdx.x == 1 ? t1 : t2);
    if (!p) return;
    float s = 0.f;
    for (int i = threadIdx.x; i < 16384; i += 256) s += fabsf(p[(size_t)i * 1792]);
    for (int o = 16; o; o >>= 1) s += __shfl_xor_sync(0xFFFFFFFFu, s, o);
    __shared__ float ws[8];
    if ((threadIdx.x & 31) == 0) ws[threadIdx.x >> 5] = s;
    __syncthreads();
    if (threadIdx.x == 0) {
        float t = 0.f;
        for (int w = 0; w < 8; w++) t += ws[w];
        g_stat[blockIdx.x] = t;
    }
}
__global__ void pick_kernel() {
    if (threadIdx.x == 0) {
        float a = g_stat[0], b = g_stat[1], c = g_stat[2];
        int w2 = (a <= b && a <= c) ? 0 : ((b <= c) ? 1 : 2);
        int f = -1, s = -1;
        for (int i = 0; i < 3; i++) if (i != w2) { if (f < 0) f = i; else s = i; }
        g_slotw2 = w2; g_slotw1 = f; g_slotw3 = s;
    }
}
__global__ void cvtx_kernel(const float* __restrict__ x) {
    if (!x) return;
    size_t i = ((size_t)blockIdx.x * 256 + threadIdx.x) * 4;
    float4 v = *(const float4*)(x + i);
    *reinterpret_cast<__half2*>(g_x16 + i)     = __floats2half2_rn(v.x, v.y);
    *reinterpret_cast<__half2*>(g_x16 + i + 2) = __floats2half2_rn(v.z, v.w);
}
__global__ void router_kernel(const float* __restrict__ x, const float* __restrict__ gw) {
    if (!x || !gw) return;
    __shared__ float gsm[NEXP * HDIM];
    int tid = threadIdx.x;
    for (int i = tid; i < NEXP * HDIM; i += 256) gsm[i] = gw[i];
    __syncthreads();
    int t = blockIdx.x * 8 + (tid >> 5), lane = tid & 31;
    const float* xr = x + (size_t)t * HDIM;
    float acc[NEXP];
#pragma unroll
    for (int e = 0; e < NEXP; e++) acc[e] = 0.f;
    for (int h = lane; h < HDIM; h += 32) {
        float xv = xr[h];
#pragma unroll
        for (int e = 0; e < NEXP; e++) acc[e] += xv * gsm[e * HDIM + h];
    }
#pragma unroll
    for (int e = 0; e < NEXP; e++)
        for (int o = 16; o; o >>= 1) acc[e] += __shfl_xor_sync(0xFFFFFFFFu, acc[e], o);
    if (lane == 0) {
        float m = acc[0];
#pragma unroll
        for (int e = 1; e < NEXP; e++) m = fmaxf(m, acc[e]);
        float p[NEXP];
#pragma unroll
        for (int e = 0; e < NEXP; e++) p[e] = __expf(acc[e] - m);
        int i0 = 0;
#pragma unroll
        for (int e = 1; e < NEXP; e++) if (p[e] > p[i0]) i0 = e;
        int i1 = (i0 == 0) ? 1 : 0;
#pragma unroll
        for (int e = 0; e < NEXP; e++) if (e != i0 && e != i1 && p[e] > p[i1]) i1 = e;
        float inv = 1.f / (p[i0] + p[i1]);
        g_sel[2 * t] = i0; g_sel[2 * t + 1] = i1;
        g_wgt[2 * t] = p[i0] * inv; g_wgt[2 * t + 1] = p[i1] * inv;
        atomicAdd(&g_cnt[i0], 1); atomicAdd(&g_cnt[i1], 1);
    }
}
__global__ void scan_kernel() {
    if (threadIdx.x == 0) {
        int tot = 0, mt = 0;
        g_mtp[0] = 0;
        for (int e = 0; e < NEXP; e++) {
            g_base[e] = tot;
            int pc = (g_cnt[e] + 127) & ~127;
            tot += pc; mt += pc >> 7;
            g_mtp[e + 1] = mt;
        }
    }
}
__global__ void scatter_kernel() {
    int p = blockIdx.x * 256 + threadIdx.x;
    if (p >= TOK * 2) return;
    int e = g_sel[p];
    int r = g_base[e] + atomicAdd(&g_cur[e], 1);
    g_rowtok[r] = p >> 1;
    g_rowof[p] = r;
}
__global__ void combine_kernel(float* __restrict__ out) {
    int idx = blockIdx.x * 256 + threadIdx.x;
    int t = idx >> 7, seg = idx & 127;
    int r0 = g_rowof[2 * t], r1 = g_rowof[2 * t + 1];
    float w0 = g_wgt[2 * t], w1 = g_wgt[2 * t + 1];
    const __half2* y0 = (const __half2*)(g_y + ((size_t)r0 << 10) + seg * 8);
    const __half2* y1 = (const __half2*)(g_y + ((size_t)r1 << 10) + seg * 8);
    float* dst = out + ((size_t)t << 10) + seg * 8;
#pragma unroll
    for (int j = 0; j < 4; j++) {
        float2 a = __half22float2(y0[j]);
        float2 b = __half22float2(y1[j]);
        dst[2 * j]     = w0 * a.x + w1 * b.x;
        dst[2 * j + 1] = w0 * a.y + w1 * b.y;
    }
}

// Grouped-raster, register-prefetch pipelined WMMA GEMM.
// CTA 128(M)x64(N), BK=32, double-buffered smem, 1 sync/iter.
// FUSED=1: hid = silu(x@w1)*(x@w3), K=HDIM; FUSED=0: y = hid@w2, K=IDIM.
template <int FUSED>
__global__ void __launch_bounds__(256) wmma_gemm_kernel(const float* t0, const float* t1, const float* t2) {
    constexpr int ND_ = FUSED ? IDIM : HDIM;
    constexpr int KD_ = FUSED ? HDIM : IDIM;
    constexpr int NT = ND_ / 64;
    constexpr int ABYTES = 128 * 40 * 2;               // 10240
    constexpr int BBYTES = 32 * 72 * 2;                // 4608
    constexpr int STG = ABYTES + BBYTES + (FUSED ? BBYTES : 0);
    __shared__ __align__(16) char smraw[2 * STG];

    const int tid = threadIdx.x, wid = tid >> 5, lane = tid & 31;

    // grouped rasterization: GROUP_M=8 m-tiles per n-sweep
    const int id = blockIdx.x;
    const int tpg = 8 * NT;
    const int gm_ = (id / tpg) * 8 + (id % tpg) % 8;
    const int n0 = ((id % tpg) / 8) * 64;
    if (gm_ >= g_mtp[NEXP]) return;
    int e = 0;
    while (e < NEXP - 1 && gm_ >= g_mtp[e + 1]) e++;
    const int row0 = g_base[e] + (gm_ - g_mtp[e]) * 128;

    const int s1 = FUSED ? g_slotw1 : g_slotw2;
    const float* B1f = s1 == 0 ? t0 : (s1 == 1 ? t1 : t2);
    const float* B3f = nullptr;
    if (FUSED) { const int s3 = g_slotw3; B3f = s3 == 0 ? t0 : (s3 == 1 ? t1 : t2); }
    if (!B1f || (FUSED && !B3f)) return;
    const float* B1base = B1f + (size_t)e * HDIM * IDIM + n0;
    const float* B3base = FUSED ? B3f + (size_t)e * HDIM * IDIM + n0 : nullptr;

    const int arow = tid >> 1, acol = (tid & 1) * 16;
    const __half* aRow = FUSED ? g_x16 + (size_t)g_rowtok[row0 + arow] * HDIM
                               : g_hid + (size_t)(row0 + arow) * IDIM;
    const int bk = tid >> 3, bn = (tid & 7) * 8;

    const int wm = wid & 3, wn = wid >> 2;
    wmma::fragment<wmma::accumulator, 16, 16, 16, float> c1[2][2], c3[FUSED ? 2 : 1][FUSED ? 2 : 1];
#pragma unroll
    for (int mi = 0; mi < 2; mi++)
#pragma unroll
        for (int ni = 0; ni < 2; ni++) {
            wmma::fill_fragment(c1[mi][ni], 0.f);
            if (FUSED) wmma::fill_fragment(c3[mi][ni], 0.f);
        }

    uint4 pa0, pa1;
    float4 pb0, pb1, pc0, pc1;
    const int NS = KD_ / 32;

    auto loadRegs = [&](int ks) {
        const int k0 = ks * 32;
        const uint4* s = (const uint4*)(aRow + k0 + acol);
        pa0 = s[0]; pa1 = s[1];
        const float4* s1p = (const float4*)(B1base + (size_t)(k0 + bk) * ND_ + bn);
        pb0 = s1p[0]; pb1 = s1p[1];
        if (FUSED) {
            const float4* s3p = (const float4*)(B3base + (size_t)(k0 + bk) * ND_ + bn);
            pc0 = s3p[0]; pc1 = s3p[1];
        }
    };
    auto storeSmem = [&](int buf) {
        char* base = smraw + buf * STG;
        uint4* d = (uint4*)((__half*)base + arow * 40 + acol);
        d[0] = pa0; d[1] = pa1;
        __half2* d1 = (__half2*)((__half*)(base + ABYTES) + bk * 72 + bn);
        d1[0] = __floats2half2_rn(pb0.x, pb0.y); d1[1] = __floats2half2_rn(pb0.z, pb0.w);
        d1[2] = __floats2half2_rn(pb1.x, pb1.y); d1[3] = __floats2half2_rn(pb1.z, pb1.w);
        if (FUSED) {
            __half2* d3 = (__half2*)((__half*)(base + ABYTES + BBYTES) + bk * 72 + bn);
            d3[0] = __floats2half2_rn(pc0.x, pc0.y); d3[1] = __floats2half2_rn(pc0.z, pc0.w);
            d3[2] = __floats2half2_rn(pc1.x, pc1.y); d3[3] = __floats2half2_rn(pc1.z, pc1.w);
        }
    };

    loadRegs(0);
    storeSmem(0);
    if (NS > 1) loadRegs(1);
    __syncthreads();

    for (int ks = 0; ks < NS; ks++) {
        if (ks + 1 < NS) storeSmem((ks + 1) & 1);
        if (ks + 2 < NS) loadRegs(ks + 2);
        char* base = smraw + (ks & 1) * STG;
        const __half* sA = (const __half*)base;
        const __half* sB1 = (const __half*)(base + ABYTES);
        const __half* sB3 = (const __half*)(base + ABYTES + BBYTES);
#pragma unroll
        for (int kk = 0; kk < 2; kk++) {
            wmma::fragment<wmma::matrix_a, 16, 16, 16, __half, wmma::row_major> af[2];
#pragma unroll
            for (int mi = 0; mi < 2; mi++)
                wmma::load_matrix_sync(af[mi], sA + (wm * 32 + mi * 16) * 40 + kk * 16, 40);
#pragma unroll
            for (int ni = 0; ni < 2; ni++) {
                wmma::fragment<wmma::matrix_b, 16, 16, 16, __half, wmma::row_major> bf;
                wmma::load_matrix_sync(bf, sB1 + kk * 16 * 72 + wn * 32 + ni * 16, 72);
#pragma unroll
                for (int mi = 0; mi < 2; mi++)
                    wmma::mma_sync(c1[mi][ni], af[mi], bf, c1[mi][ni]);
                if (FUSED) {
                    wmma::fragment<wmma::matrix_b, 16, 16, 16, __half, wmma::row_major> bf3;
                    wmma::load_matrix_sync(bf3, sB3 + kk * 16 * 72 + wn * 32 + ni * 16, 72);
#pragma unroll
                    for (int mi = 0; mi < 2; mi++)
                        wmma::mma_sync(c3[mi][ni], af[mi], bf3, c3[mi][ni]);
                }
            }
        }
        __syncthreads();
    }

    // epilogue: stage fragments through (now free) smem, fuse, store fp16
    float* estage = (float*)(smraw) + wid * 512;   // 8 warps * 512 floats = 16 KB < STG*2
    __half* ob = FUSED ? g_hid : g_y;
#pragma unroll
    for (int mi = 0; mi < 2; mi++)
#pragma unroll
        for (int ni = 0; ni < 2; ni++) {
            wmma::store_matrix_sync(estage, c1[mi][ni], 16, wmma::mem_row_major);
            if (FUSED) wmma::store_matrix_sync(estage + 256, c3[mi][ni], 16, wmma::mem_row_major);
            __syncwarp();
            const size_t rbase = (size_t)(row0 + wm * 32 + mi * 16);
            const int cbase = n0 + wn * 32 + ni * 16;
#pragma unroll
            for (int j = 0; j < 8; j++) {
                int idx = lane * 8 + j;
                int rr = idx >> 4, cc = idx & 15;
                float v = estage[idx];
                float hv = FUSED ? silu_f(v) * estage[256 + idx] : v;
                ob[(rbase + rr) * (size_t)ND_ + cbase + cc] = __float2half_rn(hv);
            }
            __syncwarp();
        }
}

extern "C" void kernel_launch(void* const* d_in, const int* in_sizes, int n_in,
                              void* d_out, int out_size) {
    const float* x = nullptr; const float* gw = nullptr;
    const float* trio[3] = {nullptr, nullptr, nullptr};
    int ntrio = 0;
    for (int i = 0; i < n_in; i++) {
        long long s = in_sizes[i];
        if (s == 16777216LL || s == 67108864LL) { if (!x) x = (const float*)d_in[i]; }
        else if (s == 8192LL || s == 32768LL) { if (!gw) gw = (const float*)d_in[i]; }
        else if ((s == WELEM || s == WELEM * 4) && ntrio < 3) trio[ntrio++] = (const float*)d_in[i];
    }
    if (!x || !gw || ntrio != 3) {
        if (n_in >= 5) {
            x = (const float*)d_in[0]; gw = (const float*)d_in[1];
            trio[0] = (const float*)d_in[2]; trio[1] = (const float*)d_in[3];
            trio[2] = (const float*)d_in[4]; ntrio = 3;
        }
    }
    float* out = (float*)d_out;

    sentinel_kernel<<<TOK * HDIM / 1024, 256>>>(out);
    init_kernel<<<1, 32>>>();
    fill_rowtok_kernel<<<(MAXROWS + 255) / 256, 256>>>();
    stat_kernel<<<3, 256>>>(trio[0], trio[1], trio[2]);
    pick_kernel<<<1, 32>>>();
    cvtx_kernel<<<TOK * HDIM / 1024, 256>>>(x);
    router_kernel<<<TOK / 8, 256>>>(x, gw);
    scan_kernel<<<1, 1>>>();
    scatter_kernel<<<TOK * 2 / 256, 256>>>();
    wmma_gemm_kernel<1><<<MAXMT * (IDIM / 64), 256>>>(trio[0], trio[1], trio[2]);
    wmma_gemm_kernel<0><<<MAXMT * (HDIM / 64), 256>>>(trio[0], trio[1], trio[2]);
    combine_kernel<<<TOK * 128 / 256, 256>>>(out);
}

// round 10
// speedup vs baseline: 1.2362x; 1.1469x over previous
#include <cuda_runtime.h>
#include <cuda_fp16.h>
#include <mma.h>
#include <cstdint>

using namespace nvcuda;

#define TOK 16384
#define HDIM 1024
#define IDIM 3584
#define NEXP 8
#define MAXROWS 33792
#define MAXMT 264
#define WELEM 29360128LL

static __device__ __half g_x16[(size_t)TOK * HDIM];
static __device__ __half g_w1h[(size_t)NEXP * HDIM * IDIM];
static __device__ __half g_w3h[(size_t)NEXP * HDIM * IDIM];
static __device__ __half g_w2h[(size_t)NEXP * IDIM * HDIM];
static __device__ __half g_hid[(size_t)MAXROWS * IDIM];
static __device__ __half g_y [(size_t)MAXROWS * HDIM];
static __device__ int   g_sel[TOK * 2];
static __device__ float g_wgt[TOK * 2];
static __device__ int   g_rowof[TOK * 2];
static __device__ int   g_rowtok[MAXROWS];
static __device__ int   g_cnt[NEXP], g_cur[NEXP], g_base[NEXP], g_mtp[NEXP + 1];
static __device__ float g_stat[3];
static __device__ int   g_slotw1, g_slotw2, g_slotw3;

__device__ __forceinline__ float silu_f(float x) { return x / (1.f + __expf(-x)); }

__global__ void sentinel_kernel(float* __restrict__ out) {
    size_t i = ((size_t)blockIdx.x * 256 + threadIdx.x) * 4;
    *(float4*)(out + i) = make_float4(100.f, 100.f, 100.f, 100.f);
}
__global__ void init_kernel() {
    int i = threadIdx.x;
    if (i < NEXP) { g_cnt[i] = 0; g_cur[i] = 0; }
    if (i < 3) g_stat[i] = 0.f;
}
__global__ void fill_rowtok_kernel() {
    int i = blockIdx.x * 256 + threadIdx.x;
    if (i < MAXROWS) g_rowtok[i] = 0;
}
__global__ void stat_kernel(const float* t0, const float* t1, const float* t2) {
    const float* p = blockIdx.x == 0 ? t0 : (blockIdx.x == 1 ? t1 : t2);
    if (!p) return;
    float s = 0.f;
    for (int i = threadIdx.x; i < 16384; i += 256) s += fabsf(p[(size_t)i * 1792]);
    for (int o = 16; o; o >>= 1) s += __shfl_xor_sync(0xFFFFFFFFu, s, o);
    __shared__ float ws[8];
    if ((threadIdx.x & 31) == 0) ws[threadIdx.x >> 5] = s;
    __syncthreads();
    if (threadIdx.x == 0) {
        float t = 0.f;
        for (int w = 0; w < 8; w++) t += ws[w];
        g_stat[blockIdx.x] = t;
    }
}
__global__ void pick_kernel() {
    if (threadIdx.x == 0) {
        float a = g_stat[0], b = g_stat[1], c = g_stat[2];
        int w2 = (a <= b && a <= c) ? 0 : ((b <= c) ? 1 : 2);
        int f = -1, s = -1;
        for (int i = 0; i < 3; i++) if (i != w2) { if (f < 0) f = i; else s = i; }
        g_slotw2 = w2; g_slotw1 = f; g_slotw3 = s;
    }
}
// which: 0 -> w1, 1 -> w3, 2 -> w2; slot resolved on device
__global__ void cvtw_kernel(const float* t0, const float* t1, const float* t2, int which) {
    int slot = which == 0 ? g_slotw1 : (which == 1 ? g_slotw3 : g_slotw2);
    const float* src = slot == 0 ? t0 : (slot == 1 ? t1 : t2);
    __half* dst = which == 0 ? g_w1h : (which == 1 ? g_w3h : g_w2h);
    if (!src) return;
    size_t i = ((size_t)blockIdx.x * 256 + threadIdx.x) * 8;
    float4 v0 = *(const float4*)(src + i);
    float4 v1 = *(const float4*)(src + i + 4);
    __half2* d = (__half2*)(dst + i);
    d[0] = __floats2half2_rn(v0.x, v0.y); d[1] = __floats2half2_rn(v0.z, v0.w);
    d[2] = __floats2half2_rn(v1.x, v1.y); d[3] = __floats2half2_rn(v1.z, v1.w);
}
__global__ void cvtx_kernel(const float* __restrict__ x) {
    if (!x) return;
    size_t i = ((size_t)blockIdx.x * 256 + threadIdx.x) * 4;
    float4 v = *(const float4*)(x + i);
    *reinterpret_cast<__half2*>(g_x16 + i)     = __floats2half2_rn(v.x, v.y);
    *reinterpret_cast<__half2*>(g_x16 + i + 2) = __floats2half2_rn(v.z, v.w);
}
__global__ void router_kernel(const float* __restrict__ x, const float* __restrict__ gw) {
    if (!x || !gw) return;
    __shared__ float gsm[NEXP * HDIM];
    int tid = threadIdx.x;
    for (int i = tid; i < NEXP * HDIM; i += 256) gsm[i] = gw[i];
    __syncthreads();
    int t = blockIdx.x * 8 + (tid >> 5), lane = tid & 31;
    const float* xr = x + (size_t)t * HDIM;
    float acc[NEXP];
#pragma unroll
    for (int e = 0; e < NEXP; e++) acc[e] = 0.f;
    for (int h = lane; h < HDIM; h += 32) {
        float xv = xr[h];
#pragma unroll
        for (int e = 0; e < NEXP; e++) acc[e] += xv * gsm[e * HDIM + h];
    }
#pragma unroll
    for (int e = 0; e < NEXP; e++)
        for (int o = 16; o; o >>= 1) acc[e] += __shfl_xor_sync(0xFFFFFFFFu, acc[e], o);
    if (lane == 0) {
        float m = acc[0];
#pragma unroll
        for (int e = 1; e < NEXP; e++) m = fmaxf(m, acc[e]);
        float p[NEXP];
#pragma unroll
        for (int e = 0; e < NEXP; e++) p[e] = __expf(acc[e] - m);
        int i0 = 0;
#pragma unroll
        for (int e = 1; e < NEXP; e++) if (p[e] > p[i0]) i0 = e;
        int i1 = (i0 == 0) ? 1 : 0;
#pragma unroll
        for (int e = 0; e < NEXP; e++) if (e != i0 && e != i1 && p[e] > p[i1]) i1 = e;
        float inv = 1.f / (p[i0] + p[i1]);
        g_sel[2 * t] = i0; g_sel[2 * t + 1] = i1;
        g_wgt[2 * t] = p[i0] * inv; g_wgt[2 * t + 1] = p[i1] * inv;
        atomicAdd(&g_cnt[i0], 1); atomicAdd(&g_cnt[i1], 1);
    }
}
__global__ void scan_kernel() {
    if (threadIdx.x == 0) {
        int tot = 0, mt = 0;
        g_mtp[0] = 0;
        for (int e = 0; e < NEXP; e++) {
            g_base[e] = tot;
            int pc = (g_cnt[e] + 127) & ~127;
            tot += pc; mt += pc >> 7;
            g_mtp[e + 1] = mt;
        }
    }
}
__global__ void scatter_kernel() {
    int p = blockIdx.x * 256 + threadIdx.x;
    if (p >= TOK * 2) return;
    int e = g_sel[p];
    int r = g_base[e] + atomicAdd(&g_cur[e], 1);
    g_rowtok[r] = p >> 1;
    g_rowof[p] = r;
}
__global__ void combine_kernel(float* __restrict__ out) {
    int idx = blockIdx.x * 256 + threadIdx.x;
    int t = idx >> 7, seg = idx & 127;
    int r0 = g_rowof[2 * t], r1 = g_rowof[2 * t + 1];
    float w0 = g_wgt[2 * t], w1 = g_wgt[2 * t + 1];
    const __half2* y0 = (const __half2*)(g_y + ((size_t)r0 << 10) + seg * 8);
    const __half2* y1 = (const __half2*)(g_y + ((size_t)r1 << 10) + seg * 8);
    float* dst = out + ((size_t)t << 10) + seg * 8;
#pragma unroll
    for (int j = 0; j < 4; j++) {
        float2 a = __half22float2(y0[j]);
        float2 b = __half22float2(y1[j]);
        dst[2 * j]     = w0 * a.x + w1 * b.x;
        dst[2 * j + 1] = w0 * a.y + w1 * b.y;
    }
}

// WMMA grouped GEMM, CTA 128(M) x 128(N), BK=32, fp16 weights, single-buffer smem,
// register-prefetch, GROUP_M=8 raster. 8 warps 4(m)x2(n), warp tile 32x64.
// FUSED=1: hid = silu(x@w1)*(x@w3), K=HDIM; FUSED=0: y = hid@w2, K=IDIM.
template <int FUSED>
__global__ void __launch_bounds__(256) wmma_gemm_kernel() {
    constexpr int ND_ = FUSED ? IDIM : HDIM;
    constexpr int KD_ = FUSED ? HDIM : IDIM;
    constexpr int NT = ND_ / 128;
    constexpr int ASTRIDE = 40;                       // halves
    constexpr int BSTRIDE = 136;                      // halves
    constexpr int ABYTES = 128 * ASTRIDE * 2;         // 10240
    constexpr int BBYTES = 32 * BSTRIDE * 2;          // 8704
    __shared__ __align__(16) char smraw[ABYTES + BBYTES * (FUSED ? 2 : 1)];

    const int tid = threadIdx.x, wid = tid >> 5, lane = tid & 31;

    const int id = blockIdx.x;
    const int tpg = 8 * NT;
    const int gm_ = (id / tpg) * 8 + (id % tpg) % 8;
    const int n0 = ((id % tpg) / 8) * 128;
    if (gm_ >= g_mtp[NEXP]) return;
    int e = 0;
    while (e < NEXP - 1 && gm_ >= g_mtp[e + 1]) e++;
    const int row0 = g_base[e] + (gm_ - g_mtp[e]) * 128;

    const __half* B1base = (FUSED ? g_w1h : g_w2h) + (size_t)e * HDIM * IDIM + n0;
    const __half* B3base = FUSED ? g_w3h + (size_t)e * HDIM * IDIM + n0 : nullptr;

    // A copy plan: 256 thr, row=tid>>1, 16 halves at (tid&1)*16
    const int arow = tid >> 1, acol = (tid & 1) * 16;
    const __half* aRow = FUSED ? g_x16 + (size_t)g_rowtok[row0 + arow] * HDIM
                               : g_hid + (size_t)(row0 + arow) * IDIM;
    // B copy plan: 256 thr, krow=tid>>3 (0..31), 16 halves at (tid&7)*16
    const int bk = tid >> 3, bn = (tid & 7) * 16;

    const int wm = wid & 3, wn = wid >> 2;
    wmma::fragment<wmma::accumulator, 16, 16, 16, float> c1[2][4], c3[FUSED ? 2 : 1][FUSED ? 4 : 1];
#pragma unroll
    for (int mi = 0; mi < 2; mi++)
#pragma unroll
        for (int ni = 0; ni < 4; ni++) {
            wmma::fill_fragment(c1[mi][ni], 0.f);
            if (FUSED) wmma::fill_fragment(c3[mi][ni], 0.f);
        }

    uint4 pa0, pa1, pb0, pb1, pc0, pc1;
    const int NS = KD_ / 32;

    auto loadRegs = [&](int ks) {
        const int k0 = ks * 32;
        const uint4* s = (const uint4*)(aRow + k0 + acol);
        pa0 = s[0]; pa1 = s[1];
        const uint4* s1p = (const uint4*)(B1base + (size_t)(k0 + bk) * ND_ + bn);
        pb0 = s1p[0]; pb1 = s1p[1];
        if (FUSED) {
            const uint4* s3p = (const uint4*)(B3base + (size_t)(k0 + bk) * ND_ + bn);
            pc0 = s3p[0]; pc1 = s3p[1];
        }
    };
    auto storeSmem = [&]() {
        uint4* d = (uint4*)((__half*)smraw + arow * ASTRIDE + acol);
        d[0] = pa0; d[1] = pa1;
        uint4* d1 = (uint4*)((__half*)(smraw + ABYTES) + bk * BSTRIDE + bn);
        d1[0] = pb0; d1[1] = pb1;
        if (FUSED) {
            uint4* d3 = (uint4*)((__half*)(smraw + ABYTES + BBYTES) + bk * BSTRIDE + bn);
            d3[0] = pc0; d3[1] = pc1;
        }
    };

    const __half* sA = (const __half*)smraw;
    const __half* sB1 = (const __half*)(smraw + ABYTES);
    const __half* sB3 = (const __half*)(smraw + ABYTES + BBYTES);

    loadRegs(0);
    for (int ks = 0; ks < NS; ks++) {
        storeSmem();
        __syncthreads();
        if (ks + 1 < NS) loadRegs(ks + 1);
#pragma unroll
        for (int kk = 0; kk < 2; kk++) {
            wmma::fragment<wmma::matrix_a, 16, 16, 16, __half, wmma::row_major> af[2];
#pragma unroll
            for (int mi = 0; mi < 2; mi++)
                wmma::load_matrix_sync(af[mi], sA + (wm * 32 + mi * 16) * ASTRIDE + kk * 16, ASTRIDE);
#pragma unroll
            for (int ni = 0; ni < 4; ni++) {
                wmma::fragment<wmma::matrix_b, 16, 16, 16, __half, wmma::row_major> bf;
                wmma::load_matrix_sync(bf, sB1 + kk * 16 * BSTRIDE + wn * 64 + ni * 16, BSTRIDE);
#pragma unroll
                for (int mi = 0; mi < 2; mi++)
                    wmma::mma_sync(c1[mi][ni], af[mi], bf, c1[mi][ni]);
                if (FUSED) {
                    wmma::fragment<wmma::matrix_b, 16, 16, 16, __half, wmma::row_major> bf3;
                    wmma::load_matrix_sync(bf3, sB3 + kk * 16 * BSTRIDE + wn * 64 + ni * 16, BSTRIDE);
#pragma unroll
                    for (int mi = 0; mi < 2; mi++)
                        wmma::mma_sync(c3[mi][ni], af[mi], bf3, c3[mi][ni]);
                }
            }
        }
        __syncthreads();
    }

    // epilogue: stage through smem (mainloop done), fuse, store fp16
    float* estage = (float*)smraw + wid * 512;   // 8 * 2KB = 16KB <= smem
    __half* ob = FUSED ? g_hid : g_y;
#pragma unroll
    for (int mi = 0; mi < 2; mi++)
#pragma unroll
        for (int ni = 0; ni < 4; ni++) {
            wmma::store_matrix_sync(estage, c1[mi][ni], 16, wmma::mem_row_major);
            if (FUSED) wmma::store_matrix_sync(estage + 256, c3[mi][ni], 16, wmma::mem_row_major);
            __syncwarp();
            const size_t rbase = (size_t)(row0 + wm * 32 + mi * 16);
            const int cbase = n0 + wn * 64 + ni * 16;
#pragma unroll
            for (int j = 0; j < 8; j++) {
                int idx = lane * 8 + j;
                int rr = idx >> 4, cc = idx & 15;
                float v = estage[idx];
                float hv = FUSED ? silu_f(v) * estage[256 + idx] : v;
                ob[(rbase + rr) * (size_t)ND_ + cbase + cc] = __float2half_rn(hv);
            }
            __syncwarp();
        }
}

extern "C" void kernel_launch(void* const* d_in, const int* in_sizes, int n_in,
                              void* d_out, int out_size) {
    const float* x = nullptr; const float* gw = nullptr;
    const float* trio[3] = {nullptr, nullptr, nullptr};
    int ntrio = 0;
    for (int i = 0; i < n_in; i++) {
        long long s = in_sizes[i];
        if (s == 16777216LL || s == 67108864LL) { if (!x) x = (const float*)d_in[i]; }
        else if (s == 8192LL || s == 32768LL) { if (!gw) gw = (const float*)d_in[i]; }
        else if ((s == WELEM || s == WELEM * 4) && ntrio < 3) trio[ntrio++] = (const float*)d_in[i];
    }
    if (!x || !gw || ntrio != 3) {
        if (n_in >= 5) {
            x = (const float*)d_in[0]; gw = (const float*)d_in[1];
            trio[0] = (const float*)d_in[2]; trio[1] = (const float*)d_in[3];
            trio[2] = (const float*)d_in[4]; ntrio = 3;
        }
    }
    float* out = (float*)d_out;

    sentinel_kernel<<<TOK * HDIM / 1024, 256>>>(out);
    init_kernel<<<1, 32>>>();
    fill_rowtok_kernel<<<(MAXROWS + 255) / 256, 256>>>();
    stat_kernel<<<3, 256>>>(trio[0], trio[1], trio[2]);
    pick_kernel<<<1, 32>>>();
    cvtw_kernel<<<WELEM / 2048, 256>>>(trio[0], trio[1], trio[2], 0);
    cvtw_kernel<<<WELEM / 2048, 256>>>(trio[0], trio[1], trio[2], 1);
    cvtw_kernel<<<WELEM / 2048, 256>>>(trio[0], trio[1], trio[2], 2);
    cvtx_kernel<<<TOK * HDIM / 1024, 256>>>(x);
    router_kernel<<<TOK / 8, 256>>>(x, gw);
    scan_kernel<<<1, 1>>>();
    scatter_kernel<<<TOK * 2 / 256, 256>>>();
    wmma_gemm_kernel<1><<<MAXMT * (IDIM / 128), 256>>>();
    wmma_gemm_kernel<0><<<MAXMT * (HDIM / 128), 256>>>();
    combine_kernel<<<TOK * 128 / 256, 256>>>(out);
}

// round 11
// speedup vs baseline: 1.4576x; 1.1791x over previous
#include <cuda_runtime.h>
#include <cuda_fp16.h>
#include <mma.h>
#include <cstdint>

using namespace nvcuda;

#define TOK 16384
#define HDIM 1024
#define IDIM 3584
#define NEXP 8
#define MAXROWS 33792
#define MAXMT 264
#define WELEM 29360128LL

static __device__ __half g_x16[(size_t)TOK * HDIM];
static __device__ __half g_w1h[(size_t)NEXP * HDIM * IDIM];
static __device__ __half g_w3h[(size_t)NEXP * HDIM * IDIM];
static __device__ __half g_w2h[(size_t)NEXP * IDIM * HDIM];
static __device__ float  g_s1 [(size_t)MAXROWS * IDIM];
static __device__ __half g_hid[(size_t)MAXROWS * IDIM];
static __device__ __half g_y [(size_t)MAXROWS * HDIM];
static __device__ int   g_sel[TOK * 2];
static __device__ float g_wgt[TOK * 2];
static __device__ int   g_rowof[TOK * 2];
static __device__ int   g_rowtok[MAXROWS];
static __device__ int   g_cnt[NEXP], g_cur[NEXP], g_base[NEXP], g_mtp[NEXP + 1];
static __device__ float g_stat[3];
static __device__ int   g_slotw1, g_slotw2, g_slotw3;

__device__ __forceinline__ float silu_f(float x) { return x / (1.f + __expf(-x)); }
__device__ __forceinline__ uint32_t smem_u32(const void* p) {
    uint32_t a;
    asm("{ .reg .u64 t; cvta.to.shared.u64 t, %1; cvt.u32.u64 %0, t; }" : "=r"(a) : "l"(p));
    return a;
}
__device__ __forceinline__ void cp16(uint32_t dst, const void* src) {
    asm volatile("cp.async.cg.shared.global [%0], [%1], 16;" :: "r"(dst), "l"(src));
}
#define CP_COMMIT() asm volatile("cp.async.commit_group;" ::: "memory")
#define CP_WAIT1()  asm volatile("cp.async.wait_group 1;" ::: "memory")
#define CP_WAIT0()  asm volatile("cp.async.wait_group 0;" ::: "memory")

__global__ void sentinel_kernel(float* __restrict__ out) {
    size_t i = ((size_t)blockIdx.x * 256 + threadIdx.x) * 4;
    *(float4*)(out + i) = make_float4(100.f, 100.f, 100.f, 100.f);
}
__global__ void init_kernel() {
    int i = threadIdx.x;
    if (i < NEXP) { g_cnt[i] = 0; g_cur[i] = 0; }
    if (i < 3) g_stat[i] = 0.f;
}
__global__ void fill_rowtok_kernel() {
    int i = blockIdx.x * 256 + threadIdx.x;
    if (i < MAXROWS) g_rowtok[i] = 0;
}
__global__ void stat_kernel(const float* t0, const float* t1, const float* t2) {
    const float* p = blockIdx.x == 0 ? t0 : (blockIdx.x == 1 ? t1 : t2);
    if (!p) return;
    float s = 0.f;
    for (int i = threadIdx.x; i < 16384; i += 256) s += fabsf(p[(size_t)i * 1792]);
    for (int o = 16; o; o >>= 1) s += __shfl_xor_sync(0xFFFFFFFFu, s, o);
    __shared__ float ws[8];
    if ((threadIdx.x & 31) == 0) ws[threadIdx.x >> 5] = s;
    __syncthreads();
    if (threadIdx.x == 0) {
        float t = 0.f;
        for (int w = 0; w < 8; w++) t += ws[w];
        g_stat[blockIdx.x] = t;
    }
}
__global__ void pick_kernel() {
    if (threadIdx.x == 0) {
        float a = g_stat[0], b = g_stat[1], c = g_stat[2];
        int w2 = (a <= b && a <= c) ? 0 : ((b <= c) ? 1 : 2);
        int f = -1, s = -1;
        for (int i = 0; i < 3; i++) if (i != w2) { if (f < 0) f = i; else s = i; }
        g_slotw2 = w2; g_slotw1 = f; g_slotw3 = s;
    }
}
__global__ void cvtw_kernel(const float* t0, const float* t1, const float* t2, int which) {
    int slot = which == 0 ? g_slotw1 : (which == 1 ? g_slotw3 : g_slotw2);
    const float* src = slot == 0 ? t0 : (slot == 1 ? t1 : t2);
    __half* dst = which == 0 ? g_w1h : (which == 1 ? g_w3h : g_w2h);
    if (!src) return;
    size_t i = ((size_t)blockIdx.x * 256 + threadIdx.x) * 8;
    float4 v0 = *(const float4*)(src + i);
    float4 v1 = *(const float4*)(src + i + 4);
    __half2* d = (__half2*)(dst + i);
    d[0] = __floats2half2_rn(v0.x, v0.y); d[1] = __floats2half2_rn(v0.z, v0.w);
    d[2] = __floats2half2_rn(v1.x, v1.y); d[3] = __floats2half2_rn(v1.z, v1.w);
}
__global__ void cvtx_kernel(const float* __restrict__ x) {
    if (!x) return;
    size_t i = ((size_t)blockIdx.x * 256 + threadIdx.x) * 4;
    float4 v = *(const float4*)(x + i);
    *reinterpret_cast<__half2*>(g_x16 + i)     = __floats2half2_rn(v.x, v.y);
    *reinterpret_cast<__half2*>(g_x16 + i + 2) = __floats2half2_rn(v.z, v.w);
}
__global__ void router_kernel(const float* __restrict__ x, const float* __restrict__ gw) {
    if (!x || !gw) return;
    __shared__ float gsm[NEXP * HDIM];
    int tid = threadIdx.x;
    for (int i = tid; i < NEXP * HDIM; i += 256) gsm[i] = gw[i];
    __syncthreads();
    int t = blockIdx.x * 8 + (tid >> 5), lane = tid & 31;
    const float* xr = x + (size_t)t * HDIM;
    float acc[NEXP];
#pragma unroll
    for (int e = 0; e < NEXP; e++) acc[e] = 0.f;
    for (int h = lane; h < HDIM; h += 32) {
        float xv = xr[h];
#pragma unroll
        for (int e = 0; e < NEXP; e++) acc[e] += xv * gsm[e * HDIM + h];
    }
#pragma unroll
    for (int e = 0; e < NEXP; e++)
        for (int o = 16; o; o >>= 1) acc[e] += __shfl_xor_sync(0xFFFFFFFFu, acc[e], o);
    if (lane == 0) {
        float m = acc[0];
#pragma unroll
        for (int e = 1; e < NEXP; e++) m = fmaxf(m, acc[e]);
        float p[NEXP];
#pragma unroll
        for (int e = 0; e < NEXP; e++) p[e] = __expf(acc[e] - m);
        int i0 = 0;
#pragma unroll
        for (int e = 1; e < NEXP; e++) if (p[e] > p[i0]) i0 = e;
        int i1 = (i0 == 0) ? 1 : 0;
#pragma unroll
        for (int e = 0; e < NEXP; e++) if (e != i0 && e != i1 && p[e] > p[i1]) i1 = e;
        float inv = 1.f / (p[i0] + p[i1]);
        g_sel[2 * t] = i0; g_sel[2 * t + 1] = i1;
        g_wgt[2 * t] = p[i0] * inv; g_wgt[2 * t + 1] = p[i1] * inv;
        atomicAdd(&g_cnt[i0], 1); atomicAdd(&g_cnt[i1], 1);
    }
}
__global__ void scan_kernel() {
    if (threadIdx.x == 0) {
        int tot = 0, mt = 0;
        g_mtp[0] = 0;
        for (int e = 0; e < NEXP; e++) {
            g_base[e] = tot;
            int pc = (g_cnt[e] + 127) & ~127;
            tot += pc; mt += pc >> 7;
            g_mtp[e + 1] = mt;
        }
    }
}
__global__ void scatter_kernel() {
    int p = blockIdx.x * 256 + threadIdx.x;
    if (p >= TOK * 2) return;
    int e = g_sel[p];
    int r = g_base[e] + atomicAdd(&g_cur[e], 1);
    g_rowtok[r] = p >> 1;
    g_rowof[p] = r;
}
__global__ void combine_kernel(float* __restrict__ out) {
    int idx = blockIdx.x * 256 + threadIdx.x;
    int t = idx >> 7, seg = idx & 127;
    int r0 = g_rowof[2 * t], r1 = g_rowof[2 * t + 1];
    float w0 = g_wgt[2 * t], w1 = g_wgt[2 * t + 1];
    const __half2* y0 = (const __half2*)(g_y + ((size_t)r0 << 10) + seg * 8);
    const __half2* y1 = (const __half2*)(g_y + ((size_t)r1 << 10) + seg * 8);
    float* dst = out + ((size_t)t << 10) + seg * 8;
#pragma unroll
    for (int j = 0; j < 4; j++) {
        float2 a = __half22float2(y0[j]);
        float2 b = __half22float2(y1[j]);
        dst[2 * j]     = w0 * a.x + w1 * b.x;
        dst[2 * j + 1] = w0 * a.y + w1 * b.y;
    }
}

// 3-pass grouped GEMM, CTA 128x128, BK=32, cp.async double-buffer, 2 CTAs/SM.
// MODE 0: s1 = x@w1 (fp32 out); MODE 1: hid = silu(s1)*(x@w3); MODE 2: y = hid@w2.
template <int MODE>
__global__ void __launch_bounds__(256, 2) wmma_pass_kernel() {
    constexpr int ND_ = (MODE == 2) ? HDIM : IDIM;
    constexpr int KD_ = (MODE == 2) ? IDIM : HDIM;
    constexpr int NT = ND_ / 128;
    constexpr int ASTRIDE = 56;                       // halves (112B, 16B-aligned, conflict-free)
    constexpr int BSTRIDE = 136;                      // halves (272B)
    constexpr int ABYTES = 128 * ASTRIDE * 2;         // 14336
    constexpr int BBYTES = 32 * BSTRIDE * 2;          // 8704
    constexpr int STG = ABYTES + BBYTES;              // 23040
    __shared__ __align__(16) char smraw[2 * STG];     // 46080 <= 48KB

    const int tid = threadIdx.x, wid = tid >> 5, lane = tid & 31;
    const int id = blockIdx.x;
    const int tpg = 8 * NT;
    const int gm_ = (id / tpg) * 8 + (id % tpg) % 8;
    const int n0 = ((id % tpg) / 8) * 128;
    if (gm_ >= g_mtp[NEXP]) return;
    int e = 0;
    while (e < NEXP - 1 && gm_ >= g_mtp[e + 1]) e++;
    const int row0 = g_base[e] + (gm_ - g_mtp[e]) * 128;

    const __half* Bw = (MODE == 0 ? g_w1h : (MODE == 1 ? g_w3h : g_w2h));
    const __half* Bbase = Bw + (size_t)e * HDIM * IDIM + n0;

    // A feed: thread -> row tid>>1, 32B chunk pair at (tid&1)*32B
    const int arow = tid >> 1;
    const int acolh = (tid & 1) * 16;                 // halves
    const __half* aRow = (MODE == 2) ? g_hid + (size_t)(row0 + arow) * IDIM
                                     : g_x16 + (size_t)g_rowtok[row0 + arow] * HDIM;
    // B feed: thread -> k-row tid>>3, 32B pair at (tid&7)*32B
    const int brow = tid >> 3;
    const int bnh = (tid & 7) * 16;                   // halves

    const uint32_t pb = smem_u32(smraw);
    const uint32_t adst = pb + arow * (ASTRIDE * 2) + acolh * 2;
    const uint32_t bdst = pb + ABYTES + brow * (BSTRIDE * 2) + bnh * 2;

    const int wm = wid & 3, wn = wid >> 2;
    wmma::fragment<wmma::accumulator, 16, 16, 16, float> c[2][4];
#pragma unroll
    for (int mi = 0; mi < 2; mi++)
#pragma unroll
        for (int ni = 0; ni < 4; ni++) wmma::fill_fragment(c[mi][ni], 0.f);

    const int NS = KD_ / 32;
    auto issueStage = [&](int ks, int buf) {
        const int k0 = ks * 32;
        const uint32_t bo = buf * STG;
        cp16(adst + bo, aRow + k0 + acolh);
        cp16(adst + bo + 16, aRow + k0 + acolh + 8);
        const __half* bsrc = Bbase + (size_t)(k0 + brow) * ND_ + bnh;
        cp16(bdst + bo, bsrc);
        cp16(bdst + bo + 16, bsrc + 8);
    };

    issueStage(0, 0);
    CP_COMMIT();
    for (int ks = 0; ks < NS; ks++) {
        if (ks + 1 < NS) { issueStage(ks + 1, (ks + 1) & 1); CP_COMMIT(); }
        if (ks + 1 < NS) { CP_WAIT1(); } else { CP_WAIT0(); }
        __syncthreads();
        const __half* sA = (const __half*)(smraw + (ks & 1) * STG);
        const __half* sB = (const __half*)(smraw + (ks & 1) * STG + ABYTES);
#pragma unroll
        for (int kk = 0; kk < 2; kk++) {
            wmma::fragment<wmma::matrix_a, 16, 16, 16, __half, wmma::row_major> af[2];
#pragma unroll
            for (int mi = 0; mi < 2; mi++)
                wmma::load_matrix_sync(af[mi], sA + (wm * 32 + mi * 16) * ASTRIDE + kk * 16, ASTRIDE);
#pragma unroll
            for (int ni = 0; ni < 4; ni++) {
                wmma::fragment<wmma::matrix_b, 16, 16, 16, __half, wmma::row_major> bf;
                wmma::load_matrix_sync(bf, sB + kk * 16 * BSTRIDE + wn * 64 + ni * 16, BSTRIDE);
#pragma unroll
                for (int mi = 0; mi < 2; mi++)
                    wmma::mma_sync(c[mi][ni], af[mi], bf, c[mi][ni]);
            }
        }
        __syncthreads();
    }

    // epilogue: stage each 16x16 fragment, vectorized global I/O
    float* estage = (float*)smraw + wid * 256;        // 8 warps * 1KB
    const int er = lane >> 1, ech = (lane & 1) * 8;   // thread's 8 consecutive cols in row er
#pragma unroll
    for (int mi = 0; mi < 2; mi++)
#pragma unroll
        for (int ni = 0; ni < 4; ni++) {
            wmma::store_matrix_sync(estage, c[mi][ni], 16, wmma::mem_row_major);
            __syncwarp();
            const size_t r_ = (size_t)(row0 + wm * 32 + mi * 16 + er);
            const int c_ = n0 + wn * 64 + ni * 16 + ech;
            float4 f0 = *(float4*)(estage + (lane >> 1) * 16 + ech);
            float4 f1 = *(float4*)(estage + (lane >> 1) * 16 + ech + 4);
            if (MODE == 0) {
                float* dst = g_s1 + r_ * IDIM + c_;
                *(float4*)dst = f0; *(float4*)(dst + 4) = f1;
            } else if (MODE == 1) {
                const float* s1p = g_s1 + r_ * IDIM + c_;
                float4 s0 = *(const float4*)s1p;
                float4 s1v = *(const float4*)(s1p + 4);
                __half2 h[4];
                h[0] = __floats2half2_rn(silu_f(s0.x) * f0.x, silu_f(s0.y) * f0.y);
                h[1] = __floats2half2_rn(silu_f(s0.z) * f0.z, silu_f(s0.w) * f0.w);
                h[2] = __floats2half2_rn(silu_f(s1v.x) * f1.x, silu_f(s1v.y) * f1.y);
                h[3] = __floats2half2_rn(silu_f(s1v.z) * f1.z, silu_f(s1v.w) * f1.w);
                *(uint4*)(g_hid + r_ * IDIM + c_) = *(uint4*)h;
            } else {
                __half2 h[4];
                h[0] = __floats2half2_rn(f0.x, f0.y); h[1] = __floats2half2_rn(f0.z, f0.w);
                h[2] = __floats2half2_rn(f1.x, f1.y); h[3] = __floats2half2_rn(f1.z, f1.w);
                *(uint4*)(g_y + r_ * HDIM + c_) = *(uint4*)h;
            }
            __syncwarp();
        }
}

extern "C" void kernel_launch(void* const* d_in, const int* in_sizes, int n_in,
                              void* d_out, int out_size) {
    const float* x = nullptr; const float* gw = nullptr;
    const float* trio[3] = {nullptr, nullptr, nullptr};
    int ntrio = 0;
    for (int i = 0; i < n_in; i++) {
        long long s = in_sizes[i];
        if (s == 16777216LL || s == 67108864LL) { if (!x) x = (const float*)d_in[i]; }
        else if (s == 8192LL || s == 32768LL) { if (!gw) gw = (const float*)d_in[i]; }
        else if ((s == WELEM || s == WELEM * 4) && ntrio < 3) trio[ntrio++] = (const float*)d_in[i];
    }
    if (!x || !gw || ntrio != 3) {
        if (n_in >= 5) {
            x = (const float*)d_in[0]; gw = (const float*)d_in[1];
            trio[0] = (const float*)d_in[2]; trio[1] = (const float*)d_in[3];
            trio[2] = (const float*)d_in[4]; ntrio = 3;
        }
    }
    float* out = (float*)d_out;

    sentinel_kernel<<<TOK * HDIM / 1024, 256>>>(out);
    init_kernel<<<1, 32>>>();
    fill_rowtok_kernel<<<(MAXROWS + 255) / 256, 256>>>();
    stat_kernel<<<3, 256>>>(trio[0], trio[1], trio[2]);
    pick_kernel<<<1, 32>>>();
    cvtw_kernel<<<WELEM / 2048, 256>>>(trio[0], trio[1], trio[2], 0);
    cvtw_kernel<<<WELEM / 2048, 256>>>(trio[0], trio[1], trio[2], 1);
    cvtw_kernel<<<WELEM / 2048, 256>>>(trio[0], trio[1], trio[2], 2);
    cvtx_kernel<<<TOK * HDIM / 1024, 256>>>(x);
    router_kernel<<<TOK / 8, 256>>>(x, gw);
    scan_kernel<<<1, 1>>>();
    scatter_kernel<<<TOK * 2 / 256, 256>>>();
    wmma_pass_kernel<0><<<MAXMT * (IDIM / 128), 256>>>();
    wmma_pass_kernel<1><<<MAXMT * (IDIM / 128), 256>>>();
    wmma_pass_kernel<2><<<MAXMT * (HDIM / 128), 256>>>();
    combine_kernel<<<TOK * 128 / 256, 256>>>(out);
}